// round 7
// baseline (speedup 1.0000x reference)
#include <cuda_runtime.h>
#include <cuda_bf16.h>
#include <math.h>
#include <stdint.h>

#define BATCH     1024
#define NF        256
#define NS        100000
#define INV_TEMP  20.0f
#define LOG2E     1.4426950408889634f
#define LN2F      0.6931471805599453f
#define SCALE2    (INV_TEMP * LOG2E)           /* logits in log2 domain */
#define SHIFT     128.0f                       /* fixed softmax shift (log2 domain) */
#define NTILE     128
#define NBLK      ((NS + NTILE - 1) / NTILE)   /* 782 */
#define MCHUNK    64
#define NCHUNKS   (BATCH / MCHUNK)             /* 16 */
#define LDSS      264                          /* 256 + 8 bf16 pad */

#define SM_A      0                                    /* [64][264] bf16  = 33792 */
#define SM_B      (MCHUNK * LDSS * 2)                  /* [128][264] bf16 = 67584 */
#define SM_RED    (SM_B + NTILE * LDSS * 2)            /* [64][8] float   = 2048  */
#define SMEM_BYTES (SM_RED + MCHUNK * 8 * 4 + 64)      /* ~103.5 KB -> 2 CTAs/SM */

__device__ __nv_bfloat16 g_a_bf16[BATCH * NF];
__device__ float g_ps[(size_t)NBLK * BATCH];   /* fixed-shift partial sums */
__device__ float g_tlogit[BATCH];              /* natural-domain */
__device__ float g_rownll[BATCH];
__device__ int   g_tstride;

// ---------------------------------------------------------------- helpers
__device__ __forceinline__ uint32_t sptr(const void* p) {
    return (uint32_t)__cvta_generic_to_shared(p);
}
__device__ __forceinline__ void ldsm4(uint32_t addr, uint32_t& r0, uint32_t& r1,
                                      uint32_t& r2, uint32_t& r3) {
    asm volatile("ldmatrix.sync.aligned.m8n8.x4.shared.b16 {%0,%1,%2,%3}, [%4];"
                 : "=r"(r0), "=r"(r1), "=r"(r2), "=r"(r3) : "r"(addr));
}
__device__ __forceinline__ void mma16816(float c[4], const uint32_t a[4],
                                         uint32_t b0, uint32_t b1) {
    asm volatile(
        "mma.sync.aligned.m16n8k16.row.col.f32.bf16.bf16.f32 "
        "{%0,%1,%2,%3},{%4,%5,%6,%7},{%8,%9},{%0,%1,%2,%3};"
        : "+f"(c[0]), "+f"(c[1]), "+f"(c[2]), "+f"(c[3])
        : "r"(a[0]), "r"(a[1]), "r"(a[2]), "r"(a[3]), "r"(b0), "r"(b1));
}
#define CP_ASYNC16(dst, src) \
    asm volatile("cp.async.cg.shared.global [%0], [%1], 16;" :: "r"(dst), "l"(src) : "memory")
#define CP_COMMIT() asm volatile("cp.async.commit_group;" ::: "memory")
#define CP_WAIT0()  asm volatile("cp.async.wait_group 0;" ::: "memory")

// ---------------------------------------------------------------- prep kernels
__global__ void prep_kernel(const float* __restrict__ a) {
    int i = blockIdx.x * blockDim.x + threadIdx.x;
    if (i < BATCH * NF) g_a_bf16[i] = __float2bfloat16(a[i]);
}

__global__ void detect_kernel(const int* __restrict__ t32) {
    if (threadIdx.x == 0 && blockIdx.x == 0) {
        int s = 2;
        for (int i = 1; i < 512; i += 2)
            if (t32[i] != 0) { s = 1; break; }
        g_tstride = s;
    }
}

__global__ void tlogit_kernel(const float* __restrict__ a,
                              const int* __restrict__ t32,
                              const float* __restrict__ f) {
    int row = blockIdx.x;
    int tid = threadIdx.x;  // 256
    long long tgt = (long long)t32[row * g_tstride];
    float p = a[row * NF + tid] * f[tgt * NF + tid];
    for (int off = 16; off; off >>= 1) p += __shfl_xor_sync(~0u, p, off);
    __shared__ float sm[8];
    if ((tid & 31) == 0) sm[tid >> 5] = p;
    __syncthreads();
    if (tid == 0) {
        float s = 0.f;
        #pragma unroll
        for (int w = 0; w < 8; w++) s += sm[w];
        g_tlogit[row] = s * INV_TEMP;
    }
}

// ---------------------------------------------------------------- fused GEMM + fixed-shift softmax partials
extern __shared__ char smem_raw[];

__global__ void __launch_bounds__(128, 2) gemm_lse_kernel(const float* __restrict__ feats) {
    __nv_bfloat16* As = (__nv_bfloat16*)(smem_raw + SM_A);   // [64][264]
    __nv_bfloat16* Bs = (__nv_bfloat16*)(smem_raw + SM_B);   // [128][264]
    float* red_s = (float*)(smem_raw + SM_RED);              // [64][8]

    const int tid  = threadIdx.x;                    // 128 threads, 4 warps
    const int lane = tid & 31, warp = tid >> 5;
    const int wm = warp & 1, wn = warp >> 1;         // 2x2 grid, 32x64 warp tiles
    const int nbase = blockIdx.x * NTILE;

    // Issue A chunk 0 via cp.async (overlaps with B conversion below)
    {
        const char* src_base = (const char*)g_a_bf16;
        #pragma unroll
        for (int it = 0; it < 16; it++) {
            int i = tid + it * 128;                  // i in [0, 2048)
            int r = i >> 5, c8 = i & 31;
            CP_ASYNC16(sptr(As + r * LDSS + c8 * 8), src_base + (size_t)r * 512 + c8 * 16);
        }
        CP_COMMIT();
    }

    // Load feature slab once (fp32 -> bf16): 128 rows; OOB rows -> 0
    for (int i = tid; i < NTILE * (NF / 4); i += 128) {
        int r  = i >> 6;
        int c4 = i & 63;
        int srow = nbase + r;
        float4 v = make_float4(0.f, 0.f, 0.f, 0.f);
        if (srow < NS) v = ((const float4*)feats)[(size_t)srow * (NF / 4) + c4];
        __nv_bfloat162 p0 = __floats2bfloat162_rn(v.x, v.y);
        __nv_bfloat162 p1 = __floats2bfloat162_rn(v.z, v.w);
        uint2 u;
        u.x = *(uint32_t*)&p0;
        u.y = *(uint32_t*)&p1;
        *(uint2*)(Bs + r * LDSS + c4 * 4) = u;
    }

    const int aRow = lane & 15,                       aKo = (lane >> 4) << 3;
    const int bRow = (lane & 7) + ((lane >> 4) << 3), bKo = ((lane >> 3) & 1) << 3;
    const int qr = lane >> 2, qc = lane & 3;

    uint32_t aAd[2], bAd[4];
    #pragma unroll
    for (int t = 0; t < 2; t++)
        aAd[t] = sptr(As + (wm * 32 + t * 16 + aRow) * LDSS + aKo);
    #pragma unroll
    for (int t = 0; t < 4; t++)
        bAd[t] = sptr(Bs + (wn * 64 + t * 16 + bRow) * LDSS + bKo);

    CP_WAIT0();
    __syncthreads();

    #pragma unroll 1
    for (int mc = 0; mc < NCHUNKS; mc++) {
        float acc[2][8][4];
        #pragma unroll
        for (int mf = 0; mf < 2; mf++)
            #pragma unroll
            for (int nf = 0; nf < 8; nf++)
                #pragma unroll
                for (int j = 0; j < 4; j++) acc[mf][nf][j] = 0.f;

        uint32_t af[2][2][4];
        uint32_t bf[2][8][2];
        #pragma unroll
        for (int t = 0; t < 2; t++)
            ldsm4(aAd[t], af[0][t][0], af[0][t][1], af[0][t][2], af[0][t][3]);
        #pragma unroll
        for (int t = 0; t < 4; t++)
            ldsm4(bAd[t], bf[0][2*t][0], bf[0][2*t][1], bf[0][2*t+1][0], bf[0][2*t+1][1]);

        #pragma unroll
        for (int ks = 0; ks < 16; ks++) {
            const int cur = ks & 1, nx = cur ^ 1;
            if (ks < 15) {
                const uint32_t off = (uint32_t)(ks + 1) * 32;
                #pragma unroll
                for (int t = 0; t < 2; t++)
                    ldsm4(aAd[t] + off, af[nx][t][0], af[nx][t][1], af[nx][t][2], af[nx][t][3]);
                #pragma unroll
                for (int t = 0; t < 4; t++)
                    ldsm4(bAd[t] + off, bf[nx][2*t][0], bf[nx][2*t][1], bf[nx][2*t+1][0], bf[nx][2*t+1][1]);
            }
            #pragma unroll
            for (int mf = 0; mf < 2; mf++)
                #pragma unroll
                for (int nf = 0; nf < 8; nf++)
                    mma16816(acc[mf][nf], af[cur][mf], bf[cur][nf][0], bf[cur][nf][1]);
        }

        __syncthreads();   // all warps done reading As for this chunk

        // Issue A chunk mc+1 (same buffer); wait after the epilogue.
        if (mc + 1 < NCHUNKS) {
            const char* src_base = (const char*)g_a_bf16 + (size_t)(mc + 1) * MCHUNK * 512;
            #pragma unroll
            for (int it = 0; it < 16; it++) {
                int i = tid + it * 128;
                int r = i >> 5, c8 = i & 31;
                CP_ASYNC16(sptr(As + r * LDSS + c8 * 8), src_base + (size_t)r * 512 + c8 * 16);
            }
            CP_COMMIT();
        }

        // fixed-shift partial sums: no max pass, no predicates (OOB cols add ~2^-128)
        #pragma unroll
        for (int mf = 0; mf < 2; mf++) {
            #pragma unroll
            for (int hi = 0; hi < 2; hi++) {
                float s = 0.f;
                #pragma unroll
                for (int nf = 0; nf < 8; nf++)
                    #pragma unroll
                    for (int j = 0; j < 2; j++)
                        s += exp2f(fmaf(acc[mf][nf][hi * 2 + j], SCALE2, -SHIFT));
                int rl = wm * 32 + mf * 16 + hi * 8 + qr;
                red_s[rl * 8 + wn * 4 + qc] = s;
            }
        }

        CP_WAIT0();
        __syncthreads();   // red partials + next A chunk visible

        // 8-way merge; overlaps the next chunk's k-loop
        if (tid < MCHUNK) {
            float S = red_s[tid * 8];
            #pragma unroll
            for (int i = 1; i < 8; i++) S += red_s[tid * 8 + i];
            int grow = mc * MCHUNK + tid;
            g_ps[(size_t)blockIdx.x * BATCH + grow] = S;
        }
    }
}

// ---------------------------------------------------------------- cross-block merge: plain sum (fixed shift)
__global__ void lse_kernel() {
    int row = blockIdx.x;
    int tid = threadIdx.x;  // 256
    float S = 0.f;
    for (int b = tid; b < NBLK; b += 256)
        S += g_ps[(size_t)b * BATCH + row];
    for (int off = 16; off; off >>= 1) S += __shfl_xor_sync(~0u, S, off);
    __shared__ float ss[8];
    if ((tid & 31) == 0) ss[tid >> 5] = S;
    __syncthreads();
    if (tid == 0) {
        float Sv = 0.f;
        #pragma unroll
        for (int i = 0; i < 8; i++) Sv += ss[i];
        g_rownll[row] = (SHIFT + log2f(Sv)) * LN2F - g_tlogit[row];
    }
}

__global__ void mean_kernel(float* __restrict__ out) {
    __shared__ float sm[32];
    int tid = threadIdx.x;  // 1024
    float v = g_rownll[tid];
    for (int off = 16; off; off >>= 1) v += __shfl_xor_sync(~0u, v, off);
    if ((tid & 31) == 0) sm[tid >> 5] = v;
    __syncthreads();
    if (tid < 32) {
        float x = sm[tid];
        for (int off = 16; off; off >>= 1) x += __shfl_xor_sync(~0u, x, off);
        if (tid == 0) out[0] = x / (float)BATCH;
    }
}

// ---------------------------------------------------------------- launch
extern "C" void kernel_launch(void* const* d_in, const int* in_sizes, int n_in,
                              void* d_out, int out_size) {
    const float* a   = (const float*)d_in[0];   // inputs   [1024,256] f32
    const int*   t32 = (const int*)d_in[1];     // targets  [1024] i64/i32
    const float* f   = (const float*)d_in[2];   // features [100000,256] f32
    float* out = (float*)d_out;

    cudaFuncSetAttribute(gemm_lse_kernel,
                         cudaFuncAttributeMaxDynamicSharedMemorySize, SMEM_BYTES);

    prep_kernel<<<(BATCH * NF + 255) / 256, 256>>>(a);
    detect_kernel<<<1, 32>>>(t32);
    tlogit_kernel<<<BATCH, 256>>>(a, t32, f);
    gemm_lse_kernel<<<NBLK, 128, SMEM_BYTES>>>(f);
    lse_kernel<<<BATCH, 256>>>();
    mean_kernel<<<1, 1024>>>(out);
}

// round 8
// speedup vs baseline: 1.4647x; 1.4647x over previous
#include <cuda_runtime.h>
#include <cuda_bf16.h>
#include <math.h>
#include <stdint.h>

#define BATCH     1024
#define NF        256
#define NS        100000
#define INV_TEMP  20.0f
#define LOG2E     1.4426950408889634f
#define LN2F      0.6931471805599453f
#define SCALE2    (INV_TEMP * LOG2E)           /* logits in log2 domain */
#define SHIFT     128.0f                       /* fixed softmax shift (log2 domain) */
#define NTILE     256
#define NBLK      ((NS + NTILE - 1) / NTILE)   /* 391 */
#define MCHUNK    64
#define NCHUNKS   (BATCH / MCHUNK)             /* 16 */
#define LDSS      264                          /* 256 + 8 bf16 pad */

#define SM_A0     0                                    /* [64][264] bf16 = 33792 */
#define SM_A1     (MCHUNK * LDSS * 2)                  /* 33792..67584 */
#define SM_B      (2 * MCHUNK * LDSS * 2)              /* [256][264] bf16 = 135168 */
#define SM_RED    (SM_B + NTILE * LDSS * 2)            /* [64][16] float = 4096 */
#define SMEM_BYTES (SM_RED + MCHUNK * 16 * 4 + 64)     /* ~202 KB, 1 CTA/SM */

__device__ __nv_bfloat16 g_a_bf16[BATCH * NF];
__device__ float g_ps[(size_t)NBLK * BATCH];   /* fixed-shift partial sums */
__device__ float g_tlogit[BATCH];              /* natural-domain */
__device__ float g_rownll[BATCH];
__device__ int   g_tstride;

// ---------------------------------------------------------------- helpers
__device__ __forceinline__ uint32_t sptr(const void* p) {
    return (uint32_t)__cvta_generic_to_shared(p);
}
__device__ __forceinline__ void ldsm4(uint32_t addr, uint32_t& r0, uint32_t& r1,
                                      uint32_t& r2, uint32_t& r3) {
    asm volatile("ldmatrix.sync.aligned.m8n8.x4.shared.b16 {%0,%1,%2,%3}, [%4];"
                 : "=r"(r0), "=r"(r1), "=r"(r2), "=r"(r3) : "r"(addr));
}
__device__ __forceinline__ void mma16816(float c[4], const uint32_t a[4],
                                         uint32_t b0, uint32_t b1) {
    asm volatile(
        "mma.sync.aligned.m16n8k16.row.col.f32.bf16.bf16.f32 "
        "{%0,%1,%2,%3},{%4,%5,%6,%7},{%8,%9},{%0,%1,%2,%3};"
        : "+f"(c[0]), "+f"(c[1]), "+f"(c[2]), "+f"(c[3])
        : "r"(a[0]), "r"(a[1]), "r"(a[2]), "r"(a[3]), "r"(b0), "r"(b1));
}
#define CP_ASYNC16(dst, src) \
    asm volatile("cp.async.cg.shared.global [%0], [%1], 16;" :: "r"(dst), "l"(src) : "memory")
#define CP_COMMIT() asm volatile("cp.async.commit_group;" ::: "memory")
#define CP_WAIT1()  asm volatile("cp.async.wait_group 1;" ::: "memory")

// ---------------------------------------------------------------- prep kernels
__global__ void prep_kernel(const float* __restrict__ a) {
    int i = blockIdx.x * blockDim.x + threadIdx.x;
    if (i < BATCH * NF) g_a_bf16[i] = __float2bfloat16(a[i]);
}

__global__ void detect_kernel(const int* __restrict__ t32) {
    if (threadIdx.x == 0 && blockIdx.x == 0) {
        int s = 2;
        for (int i = 1; i < 512; i += 2)
            if (t32[i] != 0) { s = 1; break; }
        g_tstride = s;
    }
}

__global__ void tlogit_kernel(const float* __restrict__ a,
                              const int* __restrict__ t32,
                              const float* __restrict__ f) {
    int row = blockIdx.x;
    int tid = threadIdx.x;  // 256
    long long tgt = (long long)t32[row * g_tstride];
    float p = a[row * NF + tid] * f[tgt * NF + tid];
    for (int off = 16; off; off >>= 1) p += __shfl_xor_sync(~0u, p, off);
    __shared__ float sm[8];
    if ((tid & 31) == 0) sm[tid >> 5] = p;
    __syncthreads();
    if (tid == 0) {
        float s = 0.f;
        #pragma unroll
        for (int w = 0; w < 8; w++) s += sm[w];
        g_tlogit[row] = s * INV_TEMP;
    }
}

// ---------------------------------------------------------------- fused GEMM + fixed-shift softmax partials
extern __shared__ char smem_raw[];

__global__ void __launch_bounds__(256, 1) gemm_lse_kernel(const float* __restrict__ feats) {
    __nv_bfloat16* Bs = (__nv_bfloat16*)(smem_raw + SM_B);   // [256][264]
    float* red_s = (float*)(smem_raw + SM_RED);              // [64][16]

    const int tid  = threadIdx.x;                    // 256 threads, 8 warps
    const int lane = tid & 31, warp = tid >> 5;
    const int wm = warp & 1, wn = warp >> 1;         // 2x4 grid, 32x64 warp tiles
    const int nbase = blockIdx.x * NTILE;

    // Issue A chunks 0 and 1 via cp.async (2-deep pipeline)
    #pragma unroll
    for (int pc = 0; pc < 2; pc++) {
        const char* src_base = (const char*)g_a_bf16 + (size_t)pc * MCHUNK * 512;
        char* dst = smem_raw + (pc ? SM_A1 : SM_A0);
        #pragma unroll
        for (int it = 0; it < 8; it++) {
            int i = tid + it * 256;                  // i in [0, 2048)
            int r = i >> 5, c8 = i & 31;
            CP_ASYNC16(sptr(dst + (r * LDSS + c8 * 8) * 2), src_base + (size_t)r * 512 + c8 * 16);
        }
        CP_COMMIT();
    }

    // Load feature slab once (fp32 -> bf16): 256 rows; OOB rows -> 0
    for (int i = tid; i < NTILE * (NF / 4); i += 256) {
        int r  = i >> 6;
        int c4 = i & 63;
        int srow = nbase + r;
        float4 v = make_float4(0.f, 0.f, 0.f, 0.f);
        if (srow < NS) v = ((const float4*)feats)[(size_t)srow * (NF / 4) + c4];
        __nv_bfloat162 p0 = __floats2bfloat162_rn(v.x, v.y);
        __nv_bfloat162 p1 = __floats2bfloat162_rn(v.z, v.w);
        uint2 u;
        u.x = *(uint32_t*)&p0;
        u.y = *(uint32_t*)&p1;
        *(uint2*)(Bs + r * LDSS + c4 * 4) = u;
    }

    const int aRow = lane & 15,                       aKo = (lane >> 4) << 3;
    const int bRow = (lane & 7) + ((lane >> 4) << 3), bKo = ((lane >> 3) & 1) << 3;
    const int qr = lane >> 2, qc = lane & 3;

    // A addresses for both buffers, B addresses
    uint32_t aAd[2][2], bAd[4];
    #pragma unroll
    for (int t = 0; t < 2; t++) {
        aAd[0][t] = sptr(smem_raw + SM_A0 + ((wm * 32 + t * 16 + aRow) * LDSS + aKo) * 2);
        aAd[1][t] = aAd[0][t] + (SM_A1 - SM_A0);
    }
    #pragma unroll
    for (int t = 0; t < 4; t++)
        bAd[t] = sptr(Bs + (wn * 64 + t * 16 + bRow) * LDSS + bKo);

    #pragma unroll 1
    for (int mc = 0; mc < NCHUNKS; mc++) {
        const int buf = mc & 1;
        CP_WAIT1();          // A[mc] complete (A[mc+1] may stay in flight)
        __syncthreads();     // also orders: prior merge done before red overwrite below

        float acc[2][8][4];
        #pragma unroll
        for (int mf = 0; mf < 2; mf++)
            #pragma unroll
            for (int nf = 0; nf < 8; nf++)
                #pragma unroll
                for (int j = 0; j < 4; j++) acc[mf][nf][j] = 0.f;

        uint32_t af[2][2][4];
        uint32_t bf[2][8][2];
        #pragma unroll
        for (int t = 0; t < 2; t++)
            ldsm4(aAd[buf][t], af[0][t][0], af[0][t][1], af[0][t][2], af[0][t][3]);
        #pragma unroll
        for (int t = 0; t < 4; t++)
            ldsm4(bAd[t], bf[0][2*t][0], bf[0][2*t][1], bf[0][2*t+1][0], bf[0][2*t+1][1]);

        #pragma unroll
        for (int ks = 0; ks < 16; ks++) {
            const int cur = ks & 1, nx = cur ^ 1;
            if (ks < 15) {
                const uint32_t off = (uint32_t)(ks + 1) * 32;
                #pragma unroll
                for (int t = 0; t < 2; t++)
                    ldsm4(aAd[buf][t] + off, af[nx][t][0], af[nx][t][1], af[nx][t][2], af[nx][t][3]);
                #pragma unroll
                for (int t = 0; t < 4; t++)
                    ldsm4(bAd[t] + off, bf[nx][2*t][0], bf[nx][2*t][1], bf[nx][2*t+1][0], bf[nx][2*t+1][1]);
            }
            #pragma unroll
            for (int mf = 0; mf < 2; mf++)
                #pragma unroll
                for (int nf = 0; nf < 8; nf++)
                    mma16816(acc[mf][nf], af[cur][mf], bf[cur][nf][0], bf[cur][nf][1]);
        }

        __syncthreads();     // A[mc] buffer free

        // refill this buffer with A[mc+2]
        if (mc + 2 < NCHUNKS) {
            const char* src_base = (const char*)g_a_bf16 + (size_t)(mc + 2) * MCHUNK * 512;
            char* dst = smem_raw + (buf ? SM_A1 : SM_A0);
            #pragma unroll
            for (int it = 0; it < 8; it++) {
                int i = tid + it * 256;
                int r = i >> 5, c8 = i & 31;
                CP_ASYNC16(sptr(dst + (r * LDSS + c8 * 8) * 2), src_base + (size_t)r * 512 + c8 * 16);
            }
            CP_COMMIT();
        }

        // fixed-shift partial sums: no max pass, no predicates
        #pragma unroll
        for (int mf = 0; mf < 2; mf++) {
            #pragma unroll
            for (int hi = 0; hi < 2; hi++) {
                float s = 0.f;
                #pragma unroll
                for (int nf = 0; nf < 8; nf++)
                    #pragma unroll
                    for (int j = 0; j < 2; j++)
                        s += exp2f(fmaf(acc[mf][nf][hi * 2 + j], SCALE2, -SHIFT));
                int rl = wm * 32 + mf * 16 + hi * 8 + qr;
                red_s[rl * 16 + wn * 4 + qc] = s;
            }
        }

        __syncthreads();     // red partials visible

        // 16-way merge; overlaps the next chunk's k-loop
        if (tid < MCHUNK) {
            float S = red_s[tid * 16];
            #pragma unroll
            for (int i = 1; i < 16; i++) S += red_s[tid * 16 + i];
            int grow = mc * MCHUNK + tid;
            g_ps[(size_t)blockIdx.x * BATCH + grow] = S;
        }
    }
}

// ---------------------------------------------------------------- cross-block merge: plain sum (fixed shift)
__global__ void lse_kernel() {
    int row = blockIdx.x;
    int tid = threadIdx.x;  // 256
    float S = 0.f;
    for (int b = tid; b < NBLK; b += 256)
        S += g_ps[(size_t)b * BATCH + row];
    for (int off = 16; off; off >>= 1) S += __shfl_xor_sync(~0u, S, off);
    __shared__ float ss[8];
    if ((tid & 31) == 0) ss[tid >> 5] = S;
    __syncthreads();
    if (tid == 0) {
        float Sv = 0.f;
        #pragma unroll
        for (int i = 0; i < 8; i++) Sv += ss[i];
        g_rownll[row] = (SHIFT + log2f(Sv)) * LN2F - g_tlogit[row];
    }
}

__global__ void mean_kernel(float* __restrict__ out) {
    __shared__ float sm[32];
    int tid = threadIdx.x;  // 1024
    float v = g_rownll[tid];
    for (int off = 16; off; off >>= 1) v += __shfl_xor_sync(~0u, v, off);
    if ((tid & 31) == 0) sm[tid >> 5] = v;
    __syncthreads();
    if (tid < 32) {
        float x = sm[tid];
        for (int off = 16; off; off >>= 1) x += __shfl_xor_sync(~0u, x, off);
        if (tid == 0) out[0] = x / (float)BATCH;
    }
}

// ---------------------------------------------------------------- launch
extern "C" void kernel_launch(void* const* d_in, const int* in_sizes, int n_in,
                              void* d_out, int out_size) {
    const float* a   = (const float*)d_in[0];   // inputs   [1024,256] f32
    const int*   t32 = (const int*)d_in[1];     // targets  [1024] i64/i32
    const float* f   = (const float*)d_in[2];   // features [100000,256] f32
    float* out = (float*)d_out;

    cudaFuncSetAttribute(gemm_lse_kernel,
                         cudaFuncAttributeMaxDynamicSharedMemorySize, SMEM_BYTES);

    prep_kernel<<<(BATCH * NF + 255) / 256, 256>>>(a);
    detect_kernel<<<1, 32>>>(t32);
    tlogit_kernel<<<BATCH, 256>>>(a, t32, f);
    gemm_lse_kernel<<<NBLK, 256, SMEM_BYTES>>>(f);
    lse_kernel<<<BATCH, 256>>>();
    mean_kernel<<<1, 1024>>>(out);
}

// round 9
// speedup vs baseline: 1.5638x; 1.0676x over previous
#include <cuda_runtime.h>
#include <cuda_bf16.h>
#include <math.h>
#include <stdint.h>

#define BATCH     1024
#define NF        256
#define NS        100000
#define INV_TEMP  20.0f
#define LOG2E     1.4426950408889634f
#define LN2F      0.6931471805599453f
#define SCALE2    (INV_TEMP * LOG2E)           /* folded into A at prep */
#define SHIFT     128.0f                       /* fixed softmax shift (log2 domain) */
#define NTILE     256
#define NBLK      ((NS + NTILE - 1) / NTILE)   /* 391 */
#define MCHUNK    64
#define NCHUNKS   (BATCH / MCHUNK)             /* 16 */
#define LDSS      264                          /* 256 + 8 bf16 pad */
#define REDP      17                           /* padded red row: conflict-free */

#define SM_A0     0                                    /* [64][264] bf16 = 33792 */
#define SM_A1     (MCHUNK * LDSS * 2)
#define SM_B      (2 * MCHUNK * LDSS * 2)              /* [256][264] bf16 = 135168 */
#define SM_RED    (SM_B + NTILE * LDSS * 2)            /* [64][17] float */
#define SMEM_BYTES (SM_RED + MCHUNK * REDP * 4 + 64)   /* ~207 KB */

__device__ __nv_bfloat16 g_a_bf16[BATCH * NF];   /* pre-scaled by SCALE2 */
__device__ float g_ps[(size_t)NBLK * BATCH];
__device__ float g_tlogit[BATCH];
__device__ float g_rownll[BATCH];
__device__ int   g_tstride;

// ---------------------------------------------------------------- helpers
__device__ __forceinline__ uint32_t sptr(const void* p) {
    return (uint32_t)__cvta_generic_to_shared(p);
}
__device__ __forceinline__ void ldsm4(uint32_t addr, uint32_t& r0, uint32_t& r1,
                                      uint32_t& r2, uint32_t& r3) {
    asm volatile("ldmatrix.sync.aligned.m8n8.x4.shared.b16 {%0,%1,%2,%3}, [%4];"
                 : "=r"(r0), "=r"(r1), "=r"(r2), "=r"(r3) : "r"(addr));
}
__device__ __forceinline__ void mma16816(float c[4], const uint32_t a[4],
                                         uint32_t b0, uint32_t b1) {
    asm volatile(
        "mma.sync.aligned.m16n8k16.row.col.f32.bf16.bf16.f32 "
        "{%0,%1,%2,%3},{%4,%5,%6,%7},{%8,%9},{%0,%1,%2,%3};"
        : "+f"(c[0]), "+f"(c[1]), "+f"(c[2]), "+f"(c[3])
        : "r"(a[0]), "r"(a[1]), "r"(a[2]), "r"(a[3]), "r"(b0), "r"(b1));
}
#define CP_ASYNC16(dst, src) \
    asm volatile("cp.async.cg.shared.global [%0], [%1], 16;" :: "r"(dst), "l"(src) : "memory")
#define CP_COMMIT() asm volatile("cp.async.commit_group;" ::: "memory")
#define CP_WAIT1()  asm volatile("cp.async.wait_group 1;" ::: "memory")
#define CP_WAIT0()  asm volatile("cp.async.wait_group 0;" ::: "memory")

// ---------------------------------------------------------------- prep kernels
__global__ void prep_kernel(const float* __restrict__ a) {
    int i = blockIdx.x * blockDim.x + threadIdx.x;
    if (i < BATCH * NF) g_a_bf16[i] = __float2bfloat16(a[i] * SCALE2);
}

__global__ void detect_kernel(const int* __restrict__ t32) {
    if (threadIdx.x == 0 && blockIdx.x == 0) {
        int s = 2;
        for (int i = 1; i < 512; i += 2)
            if (t32[i] != 0) { s = 1; break; }
        g_tstride = s;
    }
}

__global__ void tlogit_kernel(const float* __restrict__ a,
                              const int* __restrict__ t32,
                              const float* __restrict__ f) {
    int row = blockIdx.x;
    int tid = threadIdx.x;  // 256
    long long tgt = (long long)t32[row * g_tstride];
    float p = a[row * NF + tid] * f[tgt * NF + tid];
    for (int off = 16; off; off >>= 1) p += __shfl_xor_sync(~0u, p, off);
    __shared__ float sm[8];
    if ((tid & 31) == 0) sm[tid >> 5] = p;
    __syncthreads();
    if (tid == 0) {
        float s = 0.f;
        #pragma unroll
        for (int w = 0; w < 8; w++) s += sm[w];
        g_tlogit[row] = s * INV_TEMP;
    }
}

// ---------------------------------------------------------------- chunk body
extern __shared__ char smem_raw[];

__device__ __forceinline__ void chunk_step(
    int mc,
    float (&accC)[2][8][4], float (&accP)[2][8][4],
    const uint32_t (&aAdB)[2], const uint32_t (&bAd)[4],
    char* adst, float* red_s,
    int tid, int wm, int wn, int qr, int qc)
{
    if (mc == NCHUNKS - 1) { CP_WAIT0(); } else { CP_WAIT1(); }
    __syncthreads();                      // A[mc] ready; prior merge done

    #pragma unroll
    for (int mf = 0; mf < 2; mf++)
        #pragma unroll
        for (int nf = 0; nf < 8; nf++)
            #pragma unroll
            for (int j = 0; j < 4; j++) accC[mf][nf][j] = 0.f;

    float sprev[4] = {0.f, 0.f, 0.f, 0.f};

    uint32_t af[2][2][4];
    uint32_t bf[2][8][2];
    #pragma unroll
    for (int t = 0; t < 2; t++)
        ldsm4(aAdB[t], af[0][t][0], af[0][t][1], af[0][t][2], af[0][t][3]);
    #pragma unroll
    for (int t = 0; t < 4; t++)
        ldsm4(bAd[t], bf[0][2*t][0], bf[0][2*t][1], bf[0][2*t+1][0], bf[0][2*t+1][1]);

    #pragma unroll
    for (int ks = 0; ks < 16; ks++) {
        const int cur = ks & 1, nx = cur ^ 1;
        if (ks < 15) {
            const uint32_t off = (uint32_t)(ks + 1) * 32;
            #pragma unroll
            for (int t = 0; t < 2; t++)
                ldsm4(aAdB[t] + off, af[nx][t][0], af[nx][t][1], af[nx][t][2], af[nx][t][3]);
            #pragma unroll
            for (int t = 0; t < 4; t++)
                ldsm4(bAd[t] + off, bf[nx][2*t][0], bf[nx][2*t][1], bf[nx][2*t+1][0], bf[nx][2*t+1][1]);
        }
        // interleaved epilogue: 4 elements of the previous chunk's accumulator
        #pragma unroll
        for (int t = 0; t < 4; t++) {
            const int e = ks * 4 + t;
            const int mf = e >> 5, r = e & 31;
            const int hi = r >> 4, nf = (r >> 1) & 7, j = r & 1;
            sprev[mf * 2 + hi] += exp2f(accP[mf][nf][hi * 2 + j] - SHIFT);
        }
        #pragma unroll
        for (int mf = 0; mf < 2; mf++)
            #pragma unroll
            for (int nf = 0; nf < 8; nf++)
                mma16816(accC[mf][nf], af[cur][mf], bf[cur][nf][0], bf[cur][nf][1]);
    }

    __syncthreads();                      // A[mc] buffer free

    if (mc + 2 < NCHUNKS) {               // refill this buffer with A[mc+2]
        const char* src_base = (const char*)g_a_bf16 + (size_t)(mc + 2) * MCHUNK * 512;
        #pragma unroll
        for (int it = 0; it < 8; it++) {
            int i = tid + it * 256;
            int r = i >> 5, c8 = i & 31;
            CP_ASYNC16(sptr(adst + (r * LDSS + c8 * 8) * 2), src_base + (size_t)r * 512 + c8 * 16);
        }
        CP_COMMIT();
    }

    if (mc > 0) {                         // write prev chunk's per-quad sums
        #pragma unroll
        for (int mf = 0; mf < 2; mf++)
            #pragma unroll
            for (int hi = 0; hi < 2; hi++) {
                int rl = wm * 32 + mf * 16 + hi * 8 + qr;
                red_s[rl * REDP + wn * 4 + qc] = sprev[mf * 2 + hi];
            }
    }
    __syncthreads();
    if (mc > 0 && tid < MCHUNK) {         // merge for prev; overlaps next k-loop
        float S = red_s[tid * REDP];
        #pragma unroll
        for (int i = 1; i < 16; i++) S += red_s[tid * REDP + i];
        g_ps[(size_t)blockIdx.x * BATCH + (mc - 1) * MCHUNK + tid] = S;
    }
}

// ---------------------------------------------------------------- fused GEMM + fixed-shift softmax partials
__global__ void __launch_bounds__(256, 1) gemm_lse_kernel(const float* __restrict__ feats) {
    __nv_bfloat16* Bs = (__nv_bfloat16*)(smem_raw + SM_B);
    float* red_s = (float*)(smem_raw + SM_RED);

    const int tid  = threadIdx.x;                    // 256 threads, 8 warps
    const int lane = tid & 31, warp = tid >> 5;
    const int wm = warp & 1, wn = warp >> 1;         // 2x4 grid, 32x64 warp tiles
    const int nbase = blockIdx.x * NTILE;

    // Issue A chunks 0 and 1 (2-deep pipeline)
    #pragma unroll
    for (int pc = 0; pc < 2; pc++) {
        const char* src_base = (const char*)g_a_bf16 + (size_t)pc * MCHUNK * 512;
        char* dst = smem_raw + (pc ? SM_A1 : SM_A0);
        #pragma unroll
        for (int it = 0; it < 8; it++) {
            int i = tid + it * 256;
            int r = i >> 5, c8 = i & 31;
            CP_ASYNC16(sptr(dst + (r * LDSS + c8 * 8) * 2), src_base + (size_t)r * 512 + c8 * 16);
        }
        CP_COMMIT();
    }

    // Load feature slab once (fp32 -> bf16); OOB rows -> 0
    for (int i = tid; i < NTILE * (NF / 4); i += 256) {
        int r  = i >> 6;
        int c4 = i & 63;
        int srow = nbase + r;
        float4 v = make_float4(0.f, 0.f, 0.f, 0.f);
        if (srow < NS) v = ((const float4*)feats)[(size_t)srow * (NF / 4) + c4];
        __nv_bfloat162 p0 = __floats2bfloat162_rn(v.x, v.y);
        __nv_bfloat162 p1 = __floats2bfloat162_rn(v.z, v.w);
        uint2 u;
        u.x = *(uint32_t*)&p0;
        u.y = *(uint32_t*)&p1;
        *(uint2*)(Bs + r * LDSS + c4 * 4) = u;
    }

    const int aRow = lane & 15,                       aKo = (lane >> 4) << 3;
    const int bRow = (lane & 7) + ((lane >> 4) << 3), bKo = ((lane >> 3) & 1) << 3;
    const int qr = lane >> 2, qc = lane & 3;

    uint32_t aAd[2][2], bAd[4];
    #pragma unroll
    for (int t = 0; t < 2; t++) {
        aAd[0][t] = sptr(smem_raw + SM_A0 + ((wm * 32 + t * 16 + aRow) * LDSS + aKo) * 2);
        aAd[1][t] = aAd[0][t] + (SM_A1 - SM_A0);
    }
    #pragma unroll
    for (int t = 0; t < 4; t++)
        bAd[t] = sptr(Bs + (wn * 64 + t * 16 + bRow) * LDSS + bKo);

    float accA[2][8][4], accB[2][8][4];
    #pragma unroll
    for (int mf = 0; mf < 2; mf++)        // accB feeds chunk 0's (discarded) epilogue
        #pragma unroll
        for (int nf = 0; nf < 8; nf++)
            #pragma unroll
            for (int j = 0; j < 4; j++) accB[mf][nf][j] = 0.f;

    #pragma unroll 1
    for (int mc = 0; mc < NCHUNKS; mc += 2) {
        chunk_step(mc,     accA, accB, aAd[0], bAd, smem_raw + SM_A0, red_s, tid, wm, wn, qr, qc);
        chunk_step(mc + 1, accB, accA, aAd[1], bAd, smem_raw + SM_A1, red_s, tid, wm, wn, qr, qc);
    }

    // tail epilogue for chunk NCHUNKS-1 (in accB)
    __syncthreads();                      // last merge finished reading red_s
    {
        float s4[4] = {0.f, 0.f, 0.f, 0.f};
        #pragma unroll
        for (int mf = 0; mf < 2; mf++)
            #pragma unroll
            for (int hi = 0; hi < 2; hi++)
                #pragma unroll
                for (int nf = 0; nf < 8; nf++)
                    #pragma unroll
                    for (int j = 0; j < 2; j++)
                        s4[mf * 2 + hi] += exp2f(accB[mf][nf][hi * 2 + j] - SHIFT);
        #pragma unroll
        for (int mf = 0; mf < 2; mf++)
            #pragma unroll
            for (int hi = 0; hi < 2; hi++) {
                int rl = wm * 32 + mf * 16 + hi * 8 + qr;
                red_s[rl * REDP + wn * 4 + qc] = s4[mf * 2 + hi];
            }
        __syncthreads();
        if (tid < MCHUNK) {
            float S = red_s[tid * REDP];
            #pragma unroll
            for (int i = 1; i < 16; i++) S += red_s[tid * REDP + i];
            g_ps[(size_t)blockIdx.x * BATCH + (NCHUNKS - 1) * MCHUNK + tid] = S;
        }
    }
}

// ---------------------------------------------------------------- cross-block merge: plain sum (fixed shift)
__global__ void lse_kernel() {
    int row = blockIdx.x;
    int tid = threadIdx.x;  // 256
    float S = 0.f;
    for (int b = tid; b < NBLK; b += 256)
        S += g_ps[(size_t)b * BATCH + row];
    for (int off = 16; off; off >>= 1) S += __shfl_xor_sync(~0u, S, off);
    __shared__ float ss[8];
    if ((tid & 31) == 0) ss[tid >> 5] = S;
    __syncthreads();
    if (tid == 0) {
        float Sv = 0.f;
        #pragma unroll
        for (int i = 0; i < 8; i++) Sv += ss[i];
        g_rownll[row] = (SHIFT + log2f(Sv)) * LN2F - g_tlogit[row];
    }
}

__global__ void mean_kernel(float* __restrict__ out) {
    __shared__ float sm[32];
    int tid = threadIdx.x;  // 1024
    float v = g_rownll[tid];
    for (int off = 16; off; off >>= 1) v += __shfl_xor_sync(~0u, v, off);
    if ((tid & 31) == 0) sm[tid >> 5] = v;
    __syncthreads();
    if (tid < 32) {
        float x = sm[tid];
        for (int off = 16; off; off >>= 1) x += __shfl_xor_sync(~0u, x, off);
        if (tid == 0) out[0] = x / (float)BATCH;
    }
}

// ---------------------------------------------------------------- launch
extern "C" void kernel_launch(void* const* d_in, const int* in_sizes, int n_in,
                              void* d_out, int out_size) {
    const float* a   = (const float*)d_in[0];   // inputs   [1024,256] f32
    const int*   t32 = (const int*)d_in[1];     // targets  [1024] i64/i32
    const float* f   = (const float*)d_in[2];   // features [100000,256] f32
    float* out = (float*)d_out;

    cudaFuncSetAttribute(gemm_lse_kernel,
                         cudaFuncAttributeMaxDynamicSharedMemorySize, SMEM_BYTES);

    prep_kernel<<<(BATCH * NF + 255) / 256, 256>>>(a);
    detect_kernel<<<1, 32>>>(t32);
    tlogit_kernel<<<BATCH, 256>>>(a, t32, f);
    gemm_lse_kernel<<<NBLK, 256, SMEM_BYTES>>>(f);
    lse_kernel<<<BATCH, 256>>>();
    mean_kernel<<<1, 1024>>>(out);
}